// round 8
// baseline (speedup 1.0000x reference)
#include <cuda_runtime.h>
#include <cstdint>

#define EMB_DIM  1024
#define LN_EPS   1e-5f
#define MAX_B    8192
#define MAX_R    5120    // prepass supports up to 5120 relations

// ---------------- device scratch (no allocation allowed) ----------------
__device__ int   g_offs[MAX_R + 1];    // per-relation exclusive offsets
__device__ int   g_rows[MAX_B];        // batch indices grouped by relation
__device__ float g_stats[MAX_B][4];    // per row: [s_h0, s2_h0, s_h1, s2_h1]

// ---------------- prepass: ONE single-block kernel ----------------
// dtype sniff + histogram + scan + scatter, all in static smem (24.5 KB).
__global__ __launch_bounds__(1024)
void prepass_kernel(const int* __restrict__ w, int n_ids, int batch, int R) {
    __shared__ int hist[MAX_R];   // histogram, then reused as scatter cursor
    __shared__ int sh[1024];
    const int t = threadIdx.x;

    // dtype sniff: odd 32-bit words of first n_ids words all zero <=> int64
    int nz = 0;
    for (int i = 1 + 2 * t; i < n_ids; i += 2048) nz |= (w[i] != 0);
    const int is64 = (__syncthreads_or(nz) == 0);

    for (int i = t; i < R; i += 1024) hist[i] = 0;
    __syncthreads();
    for (int b = t; b < batch; b += 1024)
        atomicAdd(&hist[is64 ? w[2 * b] : w[b]], 1);
    __syncthreads();

    // exclusive scan: 5 elems/thread chunk + Hillis-Steele over 1024 partials
    const int base = t * 5;
    int loc[5];
    int s = 0;
#pragma unroll
    for (int i = 0; i < 5; ++i) {
        const int v = (base + i < R) ? hist[base + i] : 0;
        loc[i] = v; s += v;
    }
    sh[t] = s;
    __syncthreads();
    for (int o = 1; o < 1024; o <<= 1) {
        const int v = (t >= o) ? sh[t - o] : 0;
        __syncthreads();
        sh[t] += v;
        __syncthreads();
    }
    int run = sh[t] - s;   // exclusive prefix of this thread's chunk
#pragma unroll
    for (int i = 0; i < 5; ++i) {
        if (base + i < R) {
            g_offs[base + i] = run;   // offsets for main kernel
            hist[base + i]   = run;   // scatter cursor (own chunk only)
            run += loc[i];
        }
    }
    if (t == 1023) g_offs[R] = sh[1023];
    __syncthreads();

    for (int b = t; b < batch; b += 1024) {
        const int id  = is64 ? w[2 * b] : w[b];
        const int pos = atomicAdd(&hist[id], 1);
        g_rows[pos] = b;
    }
}

// ---------------- main: 2 CTAs per relation (no clusters) ----------------
// CTA (rel, h) stages T rows [512h, 512h+512) = 32 KB ONCE, loops over the
// relation's batch rows, writes pre-norm outputs to `out` and partial
// (sum, sumsq) to g_stats[b][2h..2h+1]. Unique writer per slot: deterministic.
__global__ __launch_bounds__(256)
void wproj_half_kernel(
    const float* __restrict__ ent_emb,   // [B, 1024]
    const float* __restrict__ tran,      // [R, 1024, 16]
    const float* __restrict__ bias,      // [R, 1024]
    float*       __restrict__ out)       // [B, 1024] (pre-norm after this kernel)
{
    const int rel   = blockIdx.x >> 1;
    const int h     = blockIdx.x & 1;
    const int start = g_offs[rel];
    const int end   = g_offs[rel + 1];
    if (start >= end) return;

    __shared__ float4 Ts4[2048];         // 32 KB: this half's 512 T rows
    __shared__ float4 Bs4[128];          // 2 KB bias half
    __shared__ float4 Es4[128];          // 2 KB entity-row half
    __shared__ float  rs[8], rs2[8];

    const int t   = threadIdx.x;
    const int q   = t & 3;               // quad lane
    const int rr  = t >> 2;              // base local row (0..63)
    const int wid = t >> 5, lid = t & 31;
    const float* Bs = reinterpret_cast<const float*>(Bs4);

    // Stage T half + bias half once per relation (streaming: no L2 reuse expected)
    const float4* Tg = reinterpret_cast<const float4*>(tran) + (size_t)rel * 4096 + h * 2048;
#pragma unroll
    for (int i = 0; i < 8; ++i)
        Ts4[t + 256 * i] = __ldcs(Tg + t + 256 * i);
    if (t < 128)
        Bs4[t] = __ldcs(reinterpret_cast<const float4*>(bias) + (size_t)rel * 256 + h * 128 + t);

    for (int row = start; row < end; ++row) {
        const int b = g_rows[row];
        __syncthreads();                 // Es reuse safety (+ first-iter Ts/Bs ordering)
        if (t < 128)
            Es4[t] = reinterpret_cast<const float4*>(ent_emb)[(size_t)b * 256 + h * 128 + t];
        __syncthreads();

        float x[8];
        float s = 0.f, s2 = 0.f;
#pragma unroll
        for (int j = 0; j < 8; ++j) {
            const int rloc = rr + 64 * j;            // local row 0..511
            const float4 tv = Ts4[rloc * 4 + q];     // warp reads 512B contiguous: conflict-free
            const float4 ev = Es4[(rloc >> 4) * 4 + q];
            float acc = tv.x * ev.x + tv.y * ev.y + tv.z * ev.z + tv.w * ev.w;
            acc += __shfl_xor_sync(0xffffffffu, acc, 1);   // quad sum -> full 16-wide dot
            acc += __shfl_xor_sync(0xffffffffu, acc, 2);
            acc += Bs[rloc];
            x[j] = acc;
            s += acc; s2 += acc * acc;               // each row counted 4x
        }

        // block reduction of partial stats (512 rows x 4 counts)
#pragma unroll
        for (int o = 16; o > 0; o >>= 1) {
            s  += __shfl_xor_sync(0xffffffffu, s,  o);
            s2 += __shfl_xor_sync(0xffffffffu, s2, o);
        }
        if (lid == 0) { rs[wid] = s; rs2[wid] = s2; }
        __syncthreads();
        if (t == 0) {
            float S = 0.f, S2 = 0.f;
#pragma unroll
            for (int i = 0; i < 8; ++i) { S += rs[i]; S2 += rs2[i]; }
            g_stats[b][2 * h]     = S;
            g_stats[b][2 * h + 1] = S2;
        }

        // write pre-norm outputs (one writer per row; 8 consecutive floats/warp)
        float* ob = out + (size_t)b * EMB_DIM + h * 512;
#pragma unroll
        for (int j = 0; j < 8; ++j) {
            if ((j & 3) == q) {
                const int rloc = rr + 64 * j;
                ob[rloc] = x[j];
            }
        }
    }
}

// ---------------- norm pass: one CTA per batch row ----------------
__global__ __launch_bounds__(256)
void norm_kernel(const float* __restrict__ ln_w,
                 const float* __restrict__ ln_b,
                 float*       __restrict__ out)
{
    const int b = blockIdx.x;
    const int t = threadIdx.x;

    const float S    = g_stats[b][0] + g_stats[b][2];   // 4 * sum over 1024
    const float S2   = g_stats[b][1] + g_stats[b][3];
    const float mean = S  * (1.0f / 4096.0f);
    const float var  = S2 * (1.0f / 4096.0f) - mean * mean;
    const float rstd = rsqrtf(var + LN_EPS);

    float4*       o4 = reinterpret_cast<float4*>(out) + (size_t)b * 256;
    const float4* w4 = reinterpret_cast<const float4*>(ln_w);
    const float4* b4 = reinterpret_cast<const float4*>(ln_b);

    float4 v = o4[t];
    const float4 w = __ldg(w4 + t);
    const float4 c = __ldg(b4 + t);
    v.x = (v.x - mean) * rstd * w.x + c.x;
    v.y = (v.y - mean) * rstd * w.y + c.y;
    v.z = (v.z - mean) * rstd * w.z + c.z;
    v.w = (v.w - mean) * rstd * w.w + c.w;
    o4[t] = v;
}

// ---------------- launch ----------------
extern "C" void kernel_launch(void* const* d_in, const int* in_sizes, int n_in,
                              void* d_out, int out_size) {
    const float* ent_emb = (const float*)d_in[0];
    const void*  ids     = d_in[1];
    const float* tran    = (const float*)d_in[2];
    const float* bias    = (const float*)d_in[3];
    const float* ln_w    = (const float*)d_in[4];
    const float* ln_b    = (const float*)d_in[5];
    float*       out     = (float*)d_out;

    const int batch = in_sizes[0] / EMB_DIM;               // 8192
    const int R     = in_sizes[2] / (EMB_DIM * 16);        // 5000
    const int n_ids = in_sizes[1];

    prepass_kernel<<<1, 1024>>>((const int*)ids, n_ids, batch, R);
    wproj_half_kernel<<<2 * R, 256>>>(ent_emb, tran, bias, out);
    norm_kernel<<<batch, 256>>>(ln_w, ln_b, out);
}

// round 11
// speedup vs baseline: 1.0529x; 1.0529x over previous
#include <cuda_runtime.h>
#include <cstdint>

#define EMB_DIM  1024
#define LN_EPS   1e-5f
#define MAX_B    8192
#define MAX_R    5120    // prepass supports up to 5120 relations

// ---------------- device scratch (no allocation allowed) ----------------
__device__ int   g_offs[MAX_R + 1];    // per-relation exclusive offsets
__device__ int   g_rows[MAX_B];        // batch indices grouped by relation
__device__ float g_stats[MAX_B][4];    // per row: [s_h0, s2_h0, s_h1, s2_h1]

// ---------------- prepass: ONE single-block kernel, shuffle-based scan ----
__global__ __launch_bounds__(1024)
void prepass_kernel(const int* __restrict__ w, int n_ids, int batch, int R) {
    __shared__ int hist[MAX_R];   // counts, then scatter cursors
    __shared__ int wsum[32];
    const int t = threadIdx.x, lid = t & 31, wid = t >> 5;

    // dtype sniff: odd 32-bit words of first n_ids words all zero <=> int64
    int nz = 0;
    for (int i = 1 + 2 * t; i < n_ids; i += 2048) nz |= (w[i] != 0);
    const int is64 = (__syncthreads_or(nz) == 0);

    for (int i = t; i < R; i += 1024) hist[i] = 0;
    __syncthreads();
    for (int b = t; b < batch; b += 1024)
        atomicAdd(&hist[is64 ? w[2 * b] : w[b]], 1);
    __syncthreads();

    // exclusive scan of hist: 5 elems/thread, warp-shuffle based (4 barriers)
    const int base = t * 5;
    int loc[5];
    int s = 0;
#pragma unroll
    for (int i = 0; i < 5; ++i) {
        const int v = (base + i < R) ? hist[base + i] : 0;
        loc[i] = v; s += v;
    }
    int ss = s;                                  // warp inclusive scan
#pragma unroll
    for (int o = 1; o < 32; o <<= 1) {
        const int v = __shfl_up_sync(~0u, ss, o);
        if (lid >= o) ss += v;
    }
    if (lid == 31) wsum[wid] = ss;
    __syncthreads();
    if (t < 32) {
        const int v = wsum[t];
        int vv = v;
#pragma unroll
        for (int o = 1; o < 32; o <<= 1) {
            const int u = __shfl_up_sync(~0u, vv, o);
            if (t >= o) vv += u;
        }
        wsum[t] = vv - v;                        // exclusive warp offset
    }
    __syncthreads();
    const int excl = wsum[wid] + (ss - s);       // thread's exclusive prefix
    int run = excl;
#pragma unroll
    for (int i = 0; i < 5; ++i) {
        if (base + i < R) { g_offs[base + i] = run; run += loc[i]; }
    }
    if (t == 1023) g_offs[R] = run;              // tail thread carries the total

    // rebuild hist as row-scatter cursors (each thread touches only its chunk)
    {
        int r2 = excl;
#pragma unroll
        for (int i = 0; i < 5; ++i) {
            if (base + i < R) { hist[base + i] = r2; r2 += loc[i]; }
        }
    }
    __syncthreads();

    // scatter batch rows grouped by relation (counting sort)
    for (int b = t; b < batch; b += 1024) {
        const int id  = is64 ? w[2 * b] : w[b];
        const int pos = atomicAdd(&hist[id], 1);
        g_rows[pos] = b;
    }
}

// ---------------- main: 2 CTAs per relation ----------------
// CTA (rel, h) stages T rows [512h, 512h+512) = 32 KB once, loops over the
// relation's grouped batch rows with Es double-buffering + register prefetch,
// writes pre-norm outputs + partial (sum, sumsq) per (b, h). Unique writer
// per slot -> deterministic.
__global__ __launch_bounds__(256)
void wproj_half_kernel(
    const float* __restrict__ ent_emb,   // [B, 1024]
    const float* __restrict__ tran,      // [R, 1024, 16]
    const float* __restrict__ bias,      // [R, 1024]
    float*       __restrict__ out)       // [B, 1024] (pre-norm after this kernel)
{
    const int rel   = blockIdx.x >> 1;
    const int h     = blockIdx.x & 1;
    const int start = g_offs[rel];
    const int end   = g_offs[rel + 1];
    if (start >= end) return;

    __shared__ float4 Ts4[2048];         // 32 KB: this half's 512 T rows
    __shared__ float4 Es4[2][128];       // 2x2 KB entity-row half, double-buffered
    __shared__ float  rs[8], rs2[8];

    const int t   = threadIdx.x;
    const int q   = t & 3;               // quad lane
    const int rr  = t >> 2;              // base local row (0..63)
    const int wid = t >> 5, lid = t & 31;

    // bias half in registers (broadcast across each quad)
    const float* Bg = bias + (size_t)rel * EMB_DIM + h * 512;
    float breg[8];
#pragma unroll
    for (int j = 0; j < 8; ++j) breg[j] = __ldg(Bg + rr + 64 * j);

    // stage T half once (streaming loads: no L2 reuse expected)
    const float4* Tg = reinterpret_cast<const float4*>(tran) + (size_t)rel * 4096 + h * 2048;
#pragma unroll
    for (int i = 0; i < 8; ++i)
        Ts4[t + 256 * i] = __ldcs(Tg + t + 256 * i);

    // prefetch first entity half into registers
    int b = g_rows[start];
    float4 epref;
    if (t < 128)
        epref = __ldg(reinterpret_cast<const float4*>(ent_emb) + (size_t)b * 256 + h * 128 + t);

    int p = 0;
    for (int row = start; row < end; ++row, p ^= 1) {
        if (t < 128) Es4[p][t] = epref;
        __syncthreads();                 // Es[p] (and Ts, first iter) visible

        // issue next row's entity prefetch before compute
        const int bn = (row + 1 < end) ? g_rows[row + 1] : b;
        if (t < 128 && row + 1 < end)
            epref = __ldg(reinterpret_cast<const float4*>(ent_emb) + (size_t)bn * 256 + h * 128 + t);

        float x[8];
        float s = 0.f, s2 = 0.f;
#pragma unroll
        for (int j = 0; j < 8; ++j) {
            const int rloc = rr + 64 * j;            // local row 0..511
            const float4 tv = Ts4[rloc * 4 + q];     // 512B contiguous per warp: conflict-free
            const float4 ev = Es4[p][(rloc >> 4) * 4 + q];
            float acc = tv.x * ev.x + tv.y * ev.y + tv.z * ev.z + tv.w * ev.w;
            acc += __shfl_xor_sync(0xffffffffu, acc, 1);   // quad sum -> 16-wide dot
            acc += __shfl_xor_sync(0xffffffffu, acc, 2);
            acc += breg[j];
            x[j] = acc;
            s += acc; s2 += acc * acc;               // each row counted 4x
        }

        // partial-stats block reduction; barrier also fences Es[p^1] for reuse
#pragma unroll
        for (int o = 16; o > 0; o >>= 1) {
            s  += __shfl_xor_sync(0xffffffffu, s,  o);
            s2 += __shfl_xor_sync(0xffffffffu, s2, o);
        }
        if (lid == 0) { rs[wid] = s; rs2[wid] = s2; }
        __syncthreads();
        if (t == 0) {
            float S = 0.f, S2 = 0.f;
#pragma unroll
            for (int i = 0; i < 8; ++i) { S += rs[i]; S2 += rs2[i]; }
            g_stats[b][2 * h]     = S;
            g_stats[b][2 * h + 1] = S2;
        }

        // pre-norm outputs: one writer/row, 8 consecutive floats per warp per j
        float* ob = out + (size_t)b * EMB_DIM + h * 512;
#pragma unroll
        for (int j = 0; j < 8; ++j) {
            if ((j & 3) == q) ob[rr + 64 * j] = x[j];
        }
        b = bn;
    }
}

// ---------------- norm pass: one CTA per batch row ----------------
__global__ __launch_bounds__(256)
void norm_kernel(const float* __restrict__ ln_w,
                 const float* __restrict__ ln_b,
                 float*       __restrict__ out)
{
    const int b = blockIdx.x;
    const int t = threadIdx.x;

    const float S    = g_stats[b][0] + g_stats[b][2];   // 4 * sum over 1024
    const float S2   = g_stats[b][1] + g_stats[b][3];
    const float mean = S  * (1.0f / 4096.0f);
    const float var  = S2 * (1.0f / 4096.0f) - mean * mean;
    const float rstd = rsqrtf(var + LN_EPS);

    float4*       o4 = reinterpret_cast<float4*>(out) + (size_t)b * 256;
    const float4* w4 = reinterpret_cast<const float4*>(ln_w);
    const float4* b4 = reinterpret_cast<const float4*>(ln_b);

    float4 v = o4[t];                    // mostly L2 hits (just written)
    const float4 w = __ldg(w4 + t);
    const float4 c = __ldg(b4 + t);
    v.x = (v.x - mean) * rstd * w.x + c.x;
    v.y = (v.y - mean) * rstd * w.y + c.y;
    v.z = (v.z - mean) * rstd * w.z + c.z;
    v.w = (v.w - mean) * rstd * w.w + c.w;
    o4[t] = v;
}

// ---------------- launch ----------------
extern "C" void kernel_launch(void* const* d_in, const int* in_sizes, int n_in,
                              void* d_out, int out_size) {
    const float* ent_emb = (const float*)d_in[0];
    const void*  ids     = d_in[1];
    const float* tran    = (const float*)d_in[2];
    const float* bias    = (const float*)d_in[3];
    const float* ln_w    = (const float*)d_in[4];
    const float* ln_b    = (const float*)d_in[5];
    float*       out     = (float*)d_out;

    const int batch = in_sizes[0] / EMB_DIM;               // 8192
    const int R     = in_sizes[2] / (EMB_DIM * 16);        // 5000
    const int n_ids = in_sizes[1];

    prepass_kernel<<<1, 1024>>>((const int*)ids, n_ids, batch, R);
    wproj_half_kernel<<<2 * R, 256>>>(ent_emb, tran, bias, out);
    norm_kernel<<<batch, 256>>>(ln_w, ln_b, out);
}